// round 5
// baseline (speedup 1.0000x reference)
#include <cuda_runtime.h>
#include <math.h>

#define Bn 1024
#define Rn 512
#define Dn 128
#define On 64

#define BETA   6.5f
#define LAM_A  0.0033f
#define LAM_W  0.003f

#define K4_CHUNKS 8

// ---------------- scratch (device globals; no allocation allowed) -------------
__device__ __align__(16) float g_S[Bn * Rn];             // s[b,r]
__device__ __align__(16) float g_SB[Bn * Rn];            // beta*s*0.5/d
__device__ __align__(16) float g_coef[Bn * Rn];          // -T[b,r]*SB[b,r]
__device__ __align__(16) float g_pa[K4_CHUNKS][Bn * Dn]; // k4 split-K partials

// ================= K1: RBF activations s[b,r] ==================================
__global__ void __launch_bounds__(256) k1_rbf(const float* __restrict__ z,
                                              const float* __restrict__ attn,
                                              const float* __restrict__ rbf)
{
    __shared__ float sr[32][33];
    __shared__ float sz[32][33];
    __shared__ float sa[32][33];

    const int tid  = threadIdx.x;
    const int tr   = tid & 15;
    const int tb   = tid >> 4;
    const int rblk = blockIdx.x << 5;
    const int bblk = blockIdx.y << 5;

    float acc[2][2];
#pragma unroll
    for (int i = 0; i < 2; ++i)
#pragma unroll
        for (int j = 0; j < 2; ++j) acc[i][j] = 0.f;

    const int lrow = tid >> 3;
    const int lcol = (tid & 7) << 2;

    for (int kc = 0; kc < 4; ++kc) {
        __syncthreads();
        const int goff = kc * 32 + lcol;
        float4 r0 = *(const float4*)(rbf  + (rblk + lrow) * Dn + goff);
        float4 z0 = *(const float4*)(z    + (bblk + lrow) * Dn + goff);
        float4 a0 = *(const float4*)(attn + (bblk + lrow) * Dn + goff);
        sr[lrow][lcol + 0] = r0.x; sr[lrow][lcol + 1] = r0.y;
        sr[lrow][lcol + 2] = r0.z; sr[lrow][lcol + 3] = r0.w;
        sz[lrow][lcol + 0] = z0.x; sz[lrow][lcol + 1] = z0.y;
        sz[lrow][lcol + 2] = z0.z; sz[lrow][lcol + 3] = z0.w;
        sa[lrow][lcol + 0] = a0.x; sa[lrow][lcol + 1] = a0.y;
        sa[lrow][lcol + 2] = a0.z; sa[lrow][lcol + 3] = a0.w;
        __syncthreads();

#pragma unroll 8
        for (int d = 0; d < 32; ++d) {
            float rv[2], zv[2], av[2];
#pragma unroll
            for (int i = 0; i < 2; ++i) rv[i] = sr[tr + 16 * i][d];
#pragma unroll
            for (int j = 0; j < 2; ++j) { zv[j] = sz[tb + 16 * j][d]; av[j] = sa[tb + 16 * j][d]; }
#pragma unroll
            for (int j = 0; j < 2; ++j)
#pragma unroll
                for (int i = 0; i < 2; ++i) {
                    float t = zv[j] - rv[i];
                    acc[i][j] = fmaf(av[j] * t, t, acc[i][j]);
                }
        }
    }

#pragma unroll
    for (int j = 0; j < 2; ++j) {
        const int b = bblk + tb + 16 * j;
#pragma unroll
        for (int i = 0; i < 2; ++i) {
            const int r = rblk + tr + 16 * i;
            float d2 = acc[i][j];
            float dd = sqrtf(d2);
            float s  = expf(-BETA * dd);
            g_S[b * Rn + r]  = s;
            g_SB[b * Rn + r] = (0.5f * BETA) * s / dd;
        }
    }
}

// ================= K23: fused x_out/G + assoc update + dL/ds ===================
// one block per batch, 512 threads. The full 128KB assoc[b] slice is staged in
// dynamic shared memory; both phases read smem. assoc: exactly 1 DRAM read +
// 1 DRAM write.
__global__ void __launch_bounds__(512) k23_fused(const float* __restrict__ assoc,
                                                 const float* __restrict__ onehot,
                                                 float* __restrict__ out_x,
                                                 float* __restrict__ out_assoc)
{
    extern __shared__ __align__(16) float4 sA[];     // 8192 float4 = 128KB
    __shared__ float sS[Rn];
    __shared__ __align__(16) float4 part[32][16];
    __shared__ __align__(16) float4 sG[16];

    const int b   = blockIdx.x;
    const int tid = threadIdx.x;
    sS[tid] = g_S[b * Rn + tid];                      // 512 threads cover Rn

    const float4* arow = (const float4*)assoc + (size_t)b * 8192;
#pragma unroll
    for (int i = 0; i < 16; ++i)
        sA[tid + 512 * i] = arow[tid + 512 * i];
    __syncthreads();

    const int oq = tid & 15;    // o quad
    const int rg = tid >> 4;    // r group 0..31

    // ---- phase 1: x_out ----
    float4 acc = make_float4(0.f, 0.f, 0.f, 0.f);
#pragma unroll
    for (int k = 0; k < 16; ++k) {
        const int r = rg + 32 * k;
        const float  s = sS[r];
        const float4 a = sA[r * 16 + oq];
        acc.x = fmaf(s, a.x, acc.x);
        acc.y = fmaf(s, a.y, acc.y);
        acc.z = fmaf(s, a.z, acc.z);
        acc.w = fmaf(s, a.w, acc.w);
    }
    part[rg][oq] = acc;
    __syncthreads();

    if (rg == 0) {
        float4 t = part[0][oq];
#pragma unroll
        for (int k = 1; k < 32; ++k) {
            float4 p = part[k][oq];
            t.x += p.x; t.y += p.y; t.z += p.z; t.w += p.w;
        }
        float xs[4] = {t.x, t.y, t.z, t.w};
        float Gs[4];
#pragma unroll
        for (int c = 0; c < 4; ++c) {
            const int o = oq * 4 + c;
            float x   = xs[c];
            float lab = onehot[b * On + o];
            float tmin  = fminf(-1.f, x);
            float teach = tmin - lab * tmin + lab * fmaxf(1.f, x);
            float e  = teach - x;
            float gd = (1.f - lab) * (x < -1.f ? 1.f : 0.f) + lab * (x > 1.f ? 1.f : 0.f);
            Gs[c] = 0.03125f * e * (gd - 1.f);   // (2/O)*e*(dT/dx - 1)
            out_x[b * On + o] = 2.f * x;         // PHI = 2
        }
        sG[oq] = make_float4(Gs[0], Gs[1], Gs[2], Gs[3]);
    }
    __syncthreads();

    // ---- phase 2: assoc update + dL/ds (all reads from smem) ----
    const float4 g = sG[oq];
    float4* orow = (float4*)out_assoc + (size_t)b * 8192;
    const float* sbrow = g_SB + b * Rn;
    float* crow = g_coef + b * Rn;

#pragma unroll
    for (int k = 0; k < 16; ++k) {
        const int r = rg + 32 * k;
        const float4 a = sA[r * 16 + oq];

        float dot = a.x * g.x;
        dot = fmaf(a.y, g.y, dot);
        dot = fmaf(a.z, g.z, dot);
        dot = fmaf(a.w, g.w, dot);
        dot += __shfl_xor_sync(0xffffffffu, dot, 8);
        dot += __shfl_xor_sync(0xffffffffu, dot, 4);
        dot += __shfl_xor_sync(0xffffffffu, dot, 2);
        dot += __shfl_xor_sync(0xffffffffu, dot, 1);

        const float sc = LAM_W * sS[r];
        float4 o4;
        o4.x = fmaf(-sc, g.x, a.x);
        o4.y = fmaf(-sc, g.y, a.y);
        o4.z = fmaf(-sc, g.z, a.z);
        o4.w = fmaf(-sc, g.w, a.w);
        orow[r * 16 + oq] = o4;

        if (oq == 0) crow[r] = -dot * sbrow[r];
    }
}

// ================= K4: attention gradient (split-K partials) ===================
__global__ void __launch_bounds__(256) k4_attn(const float* __restrict__ z,
                                               const float* __restrict__ rbf)
{
    __shared__ __align__(16) float sc[4][64];
    __shared__ float sred[4][128];

    const int tid   = threadIdx.x;
    const int j     = tid & 127;
    const int rh    = tid >> 7;
    const int bblk  = blockIdx.x << 2;
    const int rbase = blockIdx.y << 6;

    {
        const int tb = tid >> 6;
        const int r  = tid & 63;
        sc[tb][r] = g_coef[(bblk + tb) * Rn + rbase + r];
    }
    float zr[4];
#pragma unroll
    for (int tb = 0; tb < 4; ++tb) zr[tb] = z[(bblk + tb) * Dn + j];
    __syncthreads();

    float acc[4];
#pragma unroll
    for (int tb = 0; tb < 4; ++tb) acc[tb] = 0.f;

    const int r0 = rh * 32;
#pragma unroll 4
    for (int r = r0; r < r0 + 32; r += 4) {
        const float rv0 = rbf[(rbase + r + 0) * Dn + j];
        const float rv1 = rbf[(rbase + r + 1) * Dn + j];
        const float rv2 = rbf[(rbase + r + 2) * Dn + j];
        const float rv3 = rbf[(rbase + r + 3) * Dn + j];
#pragma unroll
        for (int tb = 0; tb < 4; ++tb) {
            const float4 c = *(const float4*)&sc[tb][r];
            float t;
            t = zr[tb] - rv0; acc[tb] = fmaf(c.x * t, t, acc[tb]);
            t = zr[tb] - rv1; acc[tb] = fmaf(c.y * t, t, acc[tb]);
            t = zr[tb] - rv2; acc[tb] = fmaf(c.z * t, t, acc[tb]);
            t = zr[tb] - rv3; acc[tb] = fmaf(c.w * t, t, acc[tb]);
        }
    }

    if (rh == 1) {
#pragma unroll
        for (int tb = 0; tb < 4; ++tb) sred[tb][j] = acc[tb];
    }
    __syncthreads();
    if (rh == 0) {
        float* pa = g_pa[blockIdx.y];
#pragma unroll
        for (int tb = 0; tb < 4; ++tb)
            pa[(bblk + tb) * Dn + j] = acc[tb] + sred[tb][j];
    }
}

// ================= K5: reduce partials + attention update ======================
// 256 blocks x 128 threads, 1 float4/thread, 8-deep MLP on partial reads.
__global__ void __launch_bounds__(128) k5_attn_fin(const float* __restrict__ attn,
                                                   float* __restrict__ out_attn)
{
    const int i = blockIdx.x * 128 + threadIdx.x;   // float4 index, total 32768
    const float4 a = ((const float4*)attn)[i];
    float4 p[K4_CHUNKS];
#pragma unroll
    for (int k = 0; k < K4_CHUNKS; ++k)
        p[k] = ((const float4*)g_pa[k])[i];
    float sx = 0.f, sy = 0.f, sz = 0.f, sw = 0.f;
#pragma unroll
    for (int k = 0; k < K4_CHUNKS; ++k) {
        sx += p[k].x; sy += p[k].y; sz += p[k].z; sw += p[k].w;
    }
    float4 o;
    o.x = fmaxf(fmaf(-LAM_A, sx, a.x), 0.f);
    o.y = fmaxf(fmaf(-LAM_A, sy, a.y), 0.f);
    o.z = fmaxf(fmaf(-LAM_A, sz, a.z), 0.f);
    o.w = fmaxf(fmaf(-LAM_A, sw, a.w), 0.f);
    ((float4*)out_attn)[i] = o;
}

// ================= launch ======================================================
extern "C" void kernel_launch(void* const* d_in, const int* in_sizes, int n_in,
                              void* d_out, int out_size)
{
    const float* z      = (const float*)d_in[0];  // (B,D)
    const float* onehot = (const float*)d_in[1];  // (B,O)
    const float* attn   = (const float*)d_in[2];  // (B,D)
    const float* assoc  = (const float*)d_in[3];  // (B,R,O)
    const float* rbf    = (const float*)d_in[4];  // (R,D)

    float* out       = (float*)d_out;
    float* out_x     = out;                      // B*O
    float* out_attn  = out + Bn * On;            // B*D
    float* out_assoc = out + Bn * On + Bn * Dn;  // B*R*O

    const int K23_SMEM = Rn * On * 4;            // 128KB assoc tile
    cudaFuncSetAttribute(k23_fused, cudaFuncAttributeMaxDynamicSharedMemorySize, K23_SMEM);

    k1_rbf    <<<dim3(Rn / 32, Bn / 32), 256>>>(z, attn, rbf);
    k23_fused <<<Bn, 512, K23_SMEM>>>(assoc, onehot, out_x, out_assoc);
    k4_attn   <<<dim3(Bn / 4, K4_CHUNKS), 256>>>(z, rbf);
    k5_attn_fin<<<(Bn * Dn / 4) / 128, 128>>>(attn, out_attn);
}

// round 6
// speedup vs baseline: 1.3820x; 1.3820x over previous
#include <cuda_runtime.h>
#include <math.h>

#define Bn 1024
#define Rn 512
#define Dn 128
#define On 64

#define BETA   6.5f
#define LAM_A  0.0033f
#define LAM_W  0.003f

#define K4_CHUNKS 8

// ---------------- scratch (device globals; no allocation allowed) -------------
__device__ __align__(16) float g_S[Bn * Rn];             // s[b,r]
__device__ __align__(16) float g_SB[Bn * Rn];            // beta*s*0.5/d
__device__ __align__(16) float g_Tp[2][Bn * Rn];         // partial dL/ds dots (per o-half)
__device__ __align__(16) float g_pa[K4_CHUNKS][Bn * Dn]; // k4 split-K partials

// ================= K1: RBF activations s[b,r] ==================================
__global__ void __launch_bounds__(256) k1_rbf(const float* __restrict__ z,
                                              const float* __restrict__ attn,
                                              const float* __restrict__ rbf)
{
    __shared__ float sr[32][33];
    __shared__ float sz[32][33];
    __shared__ float sa[32][33];

    const int tid  = threadIdx.x;
    const int tr   = tid & 15;
    const int tb   = tid >> 4;
    const int rblk = blockIdx.x << 5;
    const int bblk = blockIdx.y << 5;

    float acc[2][2];
#pragma unroll
    for (int i = 0; i < 2; ++i)
#pragma unroll
        for (int j = 0; j < 2; ++j) acc[i][j] = 0.f;

    const int lrow = tid >> 3;
    const int lcol = (tid & 7) << 2;

    for (int kc = 0; kc < 4; ++kc) {
        __syncthreads();
        const int goff = kc * 32 + lcol;
        float4 r0 = *(const float4*)(rbf  + (rblk + lrow) * Dn + goff);
        float4 z0 = *(const float4*)(z    + (bblk + lrow) * Dn + goff);
        float4 a0 = *(const float4*)(attn + (bblk + lrow) * Dn + goff);
        sr[lrow][lcol + 0] = r0.x; sr[lrow][lcol + 1] = r0.y;
        sr[lrow][lcol + 2] = r0.z; sr[lrow][lcol + 3] = r0.w;
        sz[lrow][lcol + 0] = z0.x; sz[lrow][lcol + 1] = z0.y;
        sz[lrow][lcol + 2] = z0.z; sz[lrow][lcol + 3] = z0.w;
        sa[lrow][lcol + 0] = a0.x; sa[lrow][lcol + 1] = a0.y;
        sa[lrow][lcol + 2] = a0.z; sa[lrow][lcol + 3] = a0.w;
        __syncthreads();

#pragma unroll 8
        for (int d = 0; d < 32; ++d) {
            float rv[2], zv[2], av[2];
#pragma unroll
            for (int i = 0; i < 2; ++i) rv[i] = sr[tr + 16 * i][d];
#pragma unroll
            for (int j = 0; j < 2; ++j) { zv[j] = sz[tb + 16 * j][d]; av[j] = sa[tb + 16 * j][d]; }
#pragma unroll
            for (int j = 0; j < 2; ++j)
#pragma unroll
                for (int i = 0; i < 2; ++i) {
                    float t = zv[j] - rv[i];
                    acc[i][j] = fmaf(av[j] * t, t, acc[i][j]);
                }
        }
    }

#pragma unroll
    for (int j = 0; j < 2; ++j) {
        const int b = bblk + tb + 16 * j;
#pragma unroll
        for (int i = 0; i < 2; ++i) {
            const int r = rblk + tr + 16 * i;
            float d2 = acc[i][j];
            float dd = sqrtf(d2);
            float s  = expf(-BETA * dd);
            g_S[b * Rn + r]  = s;
            g_SB[b * Rn + r] = (0.5f * BETA) * s / dd;
        }
    }
}

// ================= K23: fused x_out/G + assoc update + partial dL/ds ===========
// grid (Bn, 2): block (b, h) owns assoc[b, :, 32h .. 32h+31] (64KB smem tile).
// x_out and G are complete within an o-half; the dL/ds dot is written as a
// partial (g_Tp[h]) combined later in k4. assoc: exactly 1 read + 1 write.
// 256 threads, 3 blocks/SM.
__global__ void __launch_bounds__(256) k23_fused(const float* __restrict__ assoc,
                                                 const float* __restrict__ onehot,
                                                 float* __restrict__ out_x,
                                                 float* __restrict__ out_assoc)
{
    extern __shared__ __align__(16) float4 sA[];     // 4096 float4 = 64KB
    __shared__ float sS[Rn];
    __shared__ __align__(16) float4 part[32][8];
    __shared__ __align__(16) float4 sG[8];

    const int b   = blockIdx.x;
    const int oh  = blockIdx.y;                  // o-half 0/1
    const int tid = threadIdx.x;
    sS[tid]       = g_S[b * Rn + tid];
    sS[tid + 256] = g_S[b * Rn + tid + 256];

    // stage tile: rows r=0..511, 8 float4 per row (this o-half)
    const float4* abase = (const float4*)assoc + (size_t)b * 8192 + oh * 8;
#pragma unroll
    for (int it = 0; it < 16; ++it) {
        const int i  = tid + 256 * it;           // 0..4095
        const int r  = i >> 3;
        const int q  = i & 7;
        sA[i] = abase[r * 16 + q];
    }
    __syncthreads();

    const int oq = tid & 7;    // o quad within half (0..7)
    const int rg = tid >> 3;   // r group (0..31)

    // ---- phase 1: x_out for this o-half ----
    float4 acc = make_float4(0.f, 0.f, 0.f, 0.f);
#pragma unroll
    for (int k = 0; k < 16; ++k) {
        const int r = rg + 32 * k;
        const float  s = sS[r];
        const float4 a = sA[r * 8 + oq];
        acc.x = fmaf(s, a.x, acc.x);
        acc.y = fmaf(s, a.y, acc.y);
        acc.z = fmaf(s, a.z, acc.z);
        acc.w = fmaf(s, a.w, acc.w);
    }
    part[rg][oq] = acc;
    __syncthreads();

    if (rg == 0) {
        float4 t = part[0][oq];
#pragma unroll
        for (int k = 1; k < 32; ++k) {
            float4 p = part[k][oq];
            t.x += p.x; t.y += p.y; t.z += p.z; t.w += p.w;
        }
        float xs[4] = {t.x, t.y, t.z, t.w};
        float Gs[4];
#pragma unroll
        for (int c = 0; c < 4; ++c) {
            const int o = oh * 32 + oq * 4 + c;
            float x   = xs[c];
            float lab = onehot[b * On + o];
            float tmin  = fminf(-1.f, x);
            float teach = tmin - lab * tmin + lab * fmaxf(1.f, x);
            float e  = teach - x;
            float gd = (1.f - lab) * (x < -1.f ? 1.f : 0.f) + lab * (x > 1.f ? 1.f : 0.f);
            Gs[c] = 0.03125f * e * (gd - 1.f);   // (2/O)*e*(dT/dx - 1)
            out_x[b * On + o] = 2.f * x;         // PHI = 2
        }
        sG[oq] = make_float4(Gs[0], Gs[1], Gs[2], Gs[3]);
    }
    __syncthreads();

    // ---- phase 2: assoc update + partial dL/ds dot ----
    const float4 g = sG[oq];
    float4* obase = (float4*)out_assoc + (size_t)b * 8192 + oh * 8;
    float* trow = g_Tp[oh] + b * Rn;

#pragma unroll
    for (int k = 0; k < 16; ++k) {
        const int r = rg + 32 * k;
        const float4 a = sA[r * 8 + oq];

        float dot = a.x * g.x;
        dot = fmaf(a.y, g.y, dot);
        dot = fmaf(a.z, g.z, dot);
        dot = fmaf(a.w, g.w, dot);
        dot += __shfl_xor_sync(0xffffffffu, dot, 4);
        dot += __shfl_xor_sync(0xffffffffu, dot, 2);
        dot += __shfl_xor_sync(0xffffffffu, dot, 1);

        const float sc = LAM_W * sS[r];
        float4 o4;
        o4.x = fmaf(-sc, g.x, a.x);
        o4.y = fmaf(-sc, g.y, a.y);
        o4.z = fmaf(-sc, g.z, a.z);
        o4.w = fmaf(-sc, g.w, a.w);
        obase[r * 16 + oq] = o4;

        if (oq == 0) trow[r] = dot;
    }
}

// ================= K4: attention gradient (split-K partials) ===================
// combines the two Tp halves with SB on the fly: coef = -(Tp0+Tp1)*SB.
__global__ void __launch_bounds__(256) k4_attn(const float* __restrict__ z,
                                               const float* __restrict__ rbf)
{
    __shared__ __align__(16) float sc[4][64];
    __shared__ float sred[4][128];

    const int tid   = threadIdx.x;
    const int j     = tid & 127;
    const int rh    = tid >> 7;
    const int bblk  = blockIdx.x << 2;
    const int rbase = blockIdx.y << 6;

    {
        const int tb  = tid >> 6;
        const int r   = tid & 63;
        const int idx = (bblk + tb) * Rn + rbase + r;
        sc[tb][r] = -(g_Tp[0][idx] + g_Tp[1][idx]) * g_SB[idx];
    }
    float zr[4];
#pragma unroll
    for (int tb = 0; tb < 4; ++tb) zr[tb] = z[(bblk + tb) * Dn + j];
    __syncthreads();

    float acc[4];
#pragma unroll
    for (int tb = 0; tb < 4; ++tb) acc[tb] = 0.f;

    const int r0 = rh * 32;
#pragma unroll 4
    for (int r = r0; r < r0 + 32; r += 4) {
        const float rv0 = rbf[(rbase + r + 0) * Dn + j];
        const float rv1 = rbf[(rbase + r + 1) * Dn + j];
        const float rv2 = rbf[(rbase + r + 2) * Dn + j];
        const float rv3 = rbf[(rbase + r + 3) * Dn + j];
#pragma unroll
        for (int tb = 0; tb < 4; ++tb) {
            const float4 c = *(const float4*)&sc[tb][r];
            float t;
            t = zr[tb] - rv0; acc[tb] = fmaf(c.x * t, t, acc[tb]);
            t = zr[tb] - rv1; acc[tb] = fmaf(c.y * t, t, acc[tb]);
            t = zr[tb] - rv2; acc[tb] = fmaf(c.z * t, t, acc[tb]);
            t = zr[tb] - rv3; acc[tb] = fmaf(c.w * t, t, acc[tb]);
        }
    }

    if (rh == 1) {
#pragma unroll
        for (int tb = 0; tb < 4; ++tb) sred[tb][j] = acc[tb];
    }
    __syncthreads();
    if (rh == 0) {
        float* pa = g_pa[blockIdx.y];
#pragma unroll
        for (int tb = 0; tb < 4; ++tb)
            pa[(bblk + tb) * Dn + j] = acc[tb] + sred[tb][j];
    }
}

// ================= K5: reduce partials + attention update ======================
__global__ void __launch_bounds__(128) k5_attn_fin(const float* __restrict__ attn,
                                                   float* __restrict__ out_attn)
{
    const int i = blockIdx.x * 128 + threadIdx.x;   // float4 index, total 32768
    const float4 a = ((const float4*)attn)[i];
    float4 p[K4_CHUNKS];
#pragma unroll
    for (int k = 0; k < K4_CHUNKS; ++k)
        p[k] = ((const float4*)g_pa[k])[i];
    float sx = 0.f, sy = 0.f, sz = 0.f, sw = 0.f;
#pragma unroll
    for (int k = 0; k < K4_CHUNKS; ++k) {
        sx += p[k].x; sy += p[k].y; sz += p[k].z; sw += p[k].w;
    }
    float4 o;
    o.x = fmaxf(fmaf(-LAM_A, sx, a.x), 0.f);
    o.y = fmaxf(fmaf(-LAM_A, sy, a.y), 0.f);
    o.z = fmaxf(fmaf(-LAM_A, sz, a.z), 0.f);
    o.w = fmaxf(fmaf(-LAM_A, sw, a.w), 0.f);
    ((float4*)out_attn)[i] = o;
}

// ================= launch ======================================================
extern "C" void kernel_launch(void* const* d_in, const int* in_sizes, int n_in,
                              void* d_out, int out_size)
{
    const float* z      = (const float*)d_in[0];  // (B,D)
    const float* onehot = (const float*)d_in[1];  // (B,O)
    const float* attn   = (const float*)d_in[2];  // (B,D)
    const float* assoc  = (const float*)d_in[3];  // (B,R,O)
    const float* rbf    = (const float*)d_in[4];  // (R,D)

    float* out       = (float*)d_out;
    float* out_x     = out;                      // B*O
    float* out_attn  = out + Bn * On;            // B*D
    float* out_assoc = out + Bn * On + Bn * Dn;  // B*R*O

    const int K23_SMEM = Rn * 32 * 4;            // 64KB half-slice tile
    cudaFuncSetAttribute(k23_fused, cudaFuncAttributeMaxDynamicSharedMemorySize, K23_SMEM);

    k1_rbf    <<<dim3(Rn / 32, Bn / 32), 256>>>(z, attn, rbf);
    k23_fused <<<dim3(Bn, 2), 256, K23_SMEM>>>(assoc, onehot, out_x, out_assoc);
    k4_attn   <<<dim3(Bn / 4, K4_CHUNKS), 256>>>(z, rbf);
    k5_attn_fin<<<(Bn * Dn / 4) / 128, 128>>>(attn, out_attn);
}